// round 7
// baseline (speedup 1.0000x reference)
#include <cuda_runtime.h>

#define SS 2048
#define BB 2
#define DD 768
#define HH 12
#define HD 64
#define RR 64
#define E3 (3*DD)        // 2304
#define MM (SS*BB)       // 4096
#define KA (DD+RR)       // 832
#define NHEAD (BB*HH)    // 24

typedef unsigned long long u64;

// packed f32x2 helpers (FFMA2 path: only reachable via PTX on sm_103a)
__device__ __forceinline__ u64 pk2(float x, float y) {
    u64 r; asm("mov.b64 %0, {%1,%2};" : "=l"(r) : "f"(x), "f"(y)); return r;
}
__device__ __forceinline__ void upk2(u64 v, float& x, float& y) {
    asm("mov.b64 {%0,%1}, %2;" : "=f"(x), "=f"(y) : "l"(v));
}
__device__ __forceinline__ u64 fma2(u64 a, u64 b, u64 c) {
    u64 d; asm("fma.rn.f32x2 %0, %1, %2, %3;" : "=l"(d) : "l"(a), "l"(b), "l"(c)); return d;
}
__device__ __forceinline__ u64 mul2(u64 a, u64 b) {
    u64 d; asm("mul.rn.f32x2 %0, %1, %2;" : "=l"(d) : "l"(a), "l"(b)); return d;
}

// ---------------- device scratch (16B aligned for float4) ----------------
__device__ __align__(16) float g_A1[MM*KA];     // [query | relu(lora1_down)]
__device__ __align__(16) float g_A2[MM*KA];     // [attn_out | relu(lora2_down)]
__device__ __align__(16) float g_Wqkv[E3*KA];   // [in_proj*scale1 | lora1_up*ls1]
__device__ __align__(16) float g_bqkv[E3];
__device__ __align__(16) float g_Wout[DD*KA];   // [out_w*scale2 | lora2_up*ls2]
__device__ __align__(16) float g_bout[DD];
__device__ __align__(16) float g_q[NHEAD*SS*HD]; // [B*H, S, hd], pre-scaled
__device__ __align__(16) float g_k[NHEAD*SS*HD];
__device__ __align__(16) float g_v[NHEAD*SS*HD];

// ---------------- weight prep ----------------
__global__ void prep_wqkv_kernel(const float* __restrict__ W, const float* __restrict__ b,
                                 const float* __restrict__ sc, const float* __restrict__ sh,
                                 const float* __restrict__ uw, const float* __restrict__ ub,
                                 const float* __restrict__ ls) {
    int idx = blockIdx.x * 256 + threadIdx.x;
    if (idx >= E3 * KA) return;
    int n = idx / KA, k = idx - n * KA;
    float l = ls[0];
    g_Wqkv[idx] = (k < DD) ? W[n * DD + k] * sc[n] : uw[n * RR + (k - DD)] * l;
    if (k == 0) g_bqkv[n] = b[n] * sc[n] + sh[n] + ub[n] * l;
}

__global__ void prep_wout_kernel(const float* __restrict__ W, const float* __restrict__ b,
                                 const float* __restrict__ sc, const float* __restrict__ sh,
                                 const float* __restrict__ uw, const float* __restrict__ ub,
                                 const float* __restrict__ ls) {
    int idx = blockIdx.x * 256 + threadIdx.x;
    if (idx >= DD * KA) return;
    int n = idx / KA, k = idx - n * KA;
    float l = ls[0];
    g_Wout[idx] = (k < DD) ? W[n * DD + k] * sc[n] : uw[n * RR + (k - DD)] * l;
    if (k == 0) g_bout[n] = b[n] * sc[n] + sh[n] + ub[n] * l;
}

__global__ void pack_query_kernel(const float* __restrict__ q) {
    int idx = blockIdx.x * 256 + threadIdx.x;      // float4 index
    if (idx >= MM * DD / 4) return;
    int m = idx / (DD / 4), d4 = idx - m * (DD / 4);
    *(float4*)&g_A1[(size_t)m * KA + d4 * 4] = *(const float4*)(q + (size_t)m * DD + d4 * 4);
}

// ---------------- lora-down GEMM: 32x64 tiles, grid (1, MM/32)=128 blocks ------
// MODE 1: A=arg(query,lda 768) -> relu into g_A1[:,768:]
// MODE 3: A=g_A2 (lda KA)      -> relu into g_A2[:,768:]  (cols disjoint, no race)
template<int MODE>
__global__ __launch_bounds__(256) void gemm64_kernel(
    const float* __restrict__ Aarg,
    const float* __restrict__ Warg,
    const float* __restrict__ barg)
{
    const float* A = (MODE == 1) ? Aarg : g_A2;
    const int lda  = (MODE == 1) ? DD : KA;
    const float* W = Warg; const float* bias = barg;

    __shared__ float As[16][33];
    __shared__ float Bs[16][65];
    int t  = threadIdx.x;
    int tx = t & 15, ty = t >> 4;
    int m0 = blockIdx.y * 32;
    int ar = t >> 4, ak = t & 15;         // B loader coords
    int arow0 = t >> 4, akk0 = t & 15;    // A loader: elems t and t+256

    float acc[2][4];
#pragma unroll
    for (int i = 0; i < 2; i++)
#pragma unroll
        for (int j = 0; j < 4; j++) acc[i][j] = 0.f;

    for (int k0 = 0; k0 < DD; k0 += 16) {
        // A: 32x16 = 512 elems, 2 per thread
        As[akk0][arow0]      = A[(size_t)(m0 + arow0) * lda + k0 + akk0];
        As[akk0][arow0 + 16] = A[(size_t)(m0 + arow0 + 16) * lda + k0 + akk0];
        // B: 64x16 = 1024 elems, 4 per thread
#pragma unroll
        for (int p = 0; p < 4; p++)
            Bs[ak][ar + 16 * p] = W[(size_t)(ar + 16 * p) * DD + k0 + ak];
        __syncthreads();
#pragma unroll
        for (int kk = 0; kk < 16; kk++) {
            float a0 = As[kk][ty], a1 = As[kk][ty + 16];
            float bf[4];
#pragma unroll
            for (int j = 0; j < 4; j++) bf[j] = Bs[kk][tx + 16 * j];
#pragma unroll
            for (int j = 0; j < 4; j++) {
                acc[0][j] = fmaf(a0, bf[j], acc[0][j]);
                acc[1][j] = fmaf(a1, bf[j], acc[1][j]);
            }
        }
        __syncthreads();
    }

#pragma unroll
    for (int i = 0; i < 2; i++) {
        int m = m0 + ty + 16 * i;
#pragma unroll
        for (int j = 0; j < 4; j++) {
            int n = tx + 16 * j;
            float v = fmaxf(acc[i][j] + bias[n], 0.f);
            if (MODE == 1) g_A1[(size_t)m * KA + DD + n] = v;
            else           g_A2[(size_t)m * KA + DD + n] = v;
        }
    }
}

// ---------------- big GEMM: 128x128x16 double-buffered, 8x8 micro, FFMA2 -------
// MODE 2: A=g_A1, W=g_Wqkv, bias=g_bqkv -> scatter to g_q/g_k/g_v
// MODE 0: A=g_A2, W=g_Wout, bias=g_bout -> Carg (d_out, ld 768)
template<int MODE>
__global__ __launch_bounds__(256) void gemm128_kernel(float* __restrict__ Carg)
{
    const float* A    = (MODE == 2) ? g_A1   : g_A2;
    const float* W    = (MODE == 2) ? g_Wqkv : g_Wout;
    const float* bias = (MODE == 2) ? g_bqkv : g_bout;
    const int NCHUNK  = KA / 16;   // 52

    __shared__ float As[2][16][128];
    __shared__ float Bs[2][16][128];

    int t  = threadIdx.x;
    int tx = t & 15, ty = t >> 4;
    int m0 = blockIdx.y * 128, n0 = blockIdx.x * 128;

    int lrow = t >> 1;              // 0..127
    int lk   = (t & 1) * 8;         // 0 or 8

    const float* Ap = A + (size_t)(m0 + lrow) * KA + lk;
    const float* Wp = W + (size_t)(n0 + lrow) * KA + lk;

    float4 ra0, ra1, rb0, rb1;
    ra0 = *(const float4*)(Ap + 0);  ra1 = *(const float4*)(Ap + 4);
    rb0 = *(const float4*)(Wp + 0);  rb1 = *(const float4*)(Wp + 4);
#pragma unroll
    for (int j = 0; j < 4; j++) {
        As[0][lk + j][lrow]     = ((const float*)&ra0)[j];
        As[0][lk + 4 + j][lrow] = ((const float*)&ra1)[j];
        Bs[0][lk + j][lrow]     = ((const float*)&rb0)[j];
        Bs[0][lk + 4 + j][lrow] = ((const float*)&rb1)[j];
    }
    __syncthreads();

    u64 acc2[8][4];                  // 8 rows x 4 col-pairs
#pragma unroll
    for (int i = 0; i < 8; i++)
#pragma unroll
        for (int j = 0; j < 4; j++) acc2[i][j] = 0ull;

    for (int c = 0; c < NCHUNK; c++) {
        int cur = c & 1;
        if (c + 1 < NCHUNK) {
            const float* Ap2 = Ap + (c + 1) * 16;
            const float* Wp2 = Wp + (c + 1) * 16;
            ra0 = *(const float4*)(Ap2 + 0);  ra1 = *(const float4*)(Ap2 + 4);
            rb0 = *(const float4*)(Wp2 + 0);  rb1 = *(const float4*)(Wp2 + 4);
        }
#pragma unroll
        for (int kk = 0; kk < 16; kk++) {
            float4 a0 = *(const float4*)&As[cur][kk][ty * 8];
            float4 a1 = *(const float4*)&As[cur][kk][ty * 8 + 4];
            float4 b0 = *(const float4*)&Bs[cur][kk][tx * 8];
            float4 b1 = *(const float4*)&Bs[cur][kk][tx * 8 + 4];
            u64 bp[4];
            bp[0] = ((const u64*)&b0)[0];  bp[1] = ((const u64*)&b0)[1];
            bp[2] = ((const u64*)&b1)[0];  bp[3] = ((const u64*)&b1)[1];
            const float* av0 = (const float*)&a0;
            const float* av1 = (const float*)&a1;
#pragma unroll
            for (int i = 0; i < 4; i++) {
                u64 ad = pk2(av0[i], av0[i]);
#pragma unroll
                for (int j = 0; j < 4; j++)
                    acc2[i][j] = fma2(ad, bp[j], acc2[i][j]);
            }
#pragma unroll
            for (int i = 0; i < 4; i++) {
                u64 ad = pk2(av1[i], av1[i]);
#pragma unroll
                for (int j = 0; j < 4; j++)
                    acc2[i + 4][j] = fma2(ad, bp[j], acc2[i + 4][j]);
            }
        }
        if (c + 1 < NCHUNK) {
            int nxt = cur ^ 1;
#pragma unroll
            for (int j = 0; j < 4; j++) {
                As[nxt][lk + j][lrow]     = ((const float*)&ra0)[j];
                As[nxt][lk + 4 + j][lrow] = ((const float*)&ra1)[j];
                Bs[nxt][lk + j][lrow]     = ((const float*)&rb0)[j];
                Bs[nxt][lk + 4 + j][lrow] = ((const float*)&rb1)[j];
            }
            __syncthreads();
        }
    }

    // epilogue
    float bb[8];
#pragma unroll
    for (int j = 0; j < 8; j++) bb[j] = bias[n0 + tx * 8 + j];

    if (MODE == 0) {
#pragma unroll
        for (int i = 0; i < 8; i++) {
            int m = m0 + ty * 8 + i;
            float c0, c1, c2, c3, c4, c5, c6, c7;
            upk2(acc2[i][0], c0, c1); upk2(acc2[i][1], c2, c3);
            upk2(acc2[i][2], c4, c5); upk2(acc2[i][3], c6, c7);
            float4 v0 = make_float4(c0 + bb[0], c1 + bb[1], c2 + bb[2], c3 + bb[3]);
            float4 v1 = make_float4(c4 + bb[4], c5 + bb[5], c6 + bb[6], c7 + bb[7]);
            *(float4*)(Carg + (size_t)m * DD + n0 + tx * 8)     = v0;
            *(float4*)(Carg + (size_t)m * DD + n0 + tx * 8 + 4) = v1;
        }
    } else {
        int ncol = n0 + tx * 8;
        int part = ncol / DD;
        int e    = ncol - part * DD;
        int h    = e >> 6, cc = e & 63;
        float* dst = (part == 0) ? g_q : (part == 1) ? g_k : g_v;
        float scl  = (part == 0) ? 0.125f : 1.f;     // hd^-0.5 on q
#pragma unroll
        for (int i = 0; i < 8; i++) {
            int m = m0 + ty * 8 + i;
            int s = m >> 1, b = m & 1;
            float* p = dst + ((size_t)(b * HH + h) * SS + s) * HD + cc;
            float c0, c1, c2, c3, c4, c5, c6, c7;
            upk2(acc2[i][0], c0, c1); upk2(acc2[i][1], c2, c3);
            upk2(acc2[i][2], c4, c5); upk2(acc2[i][3], c6, c7);
            float4 v0 = make_float4((c0 + bb[0]) * scl, (c1 + bb[1]) * scl,
                                    (c2 + bb[2]) * scl, (c3 + bb[3]) * scl);
            float4 v1 = make_float4((c4 + bb[4]) * scl, (c5 + bb[5]) * scl,
                                    (c6 + bb[6]) * scl, (c7 + bb[7]) * scl);
            *(float4*)(p)     = v0;
            *(float4*)(p + 4) = v1;
        }
    }
}

// ---------------- flash attention: block=(head, 64 q-rows), 4x4 micro, FFMA2 ---
__global__ __launch_bounds__(256) void attn_kernel() {
    __shared__ float QsT[64 * 64];   // [h][r]
    __shared__ float KsT[64 * 64];   // [h][c]; reused as P [r][kv]
    __shared__ float Vs[64 * 64];    // [kv][c]

    int head = blockIdx.x;
    int q0   = blockIdx.y * 64;
    int t  = threadIdx.x;
    int tx = t & 15, ty = t >> 4;

    // load Q transposed: QsT[h][r] = q[r][h]
    {
        int r = t >> 2, cq0 = t & 3;
        const float* qb = g_q + ((size_t)head * SS + q0 + r) * HD;
#pragma unroll
        for (int i = 0; i < 4; i++) {
            int hq = cq0 + 4 * i;
            float4 v = *(const float4*)(qb + hq * 4);
#pragma unroll
            for (int j = 0; j < 4; j++)
                QsT[(hq * 4 + j) * 64 + r] = ((const float*)&v)[j];
        }
    }

    u64 o2[4][2];                    // 4 rows x 2 col-pairs (cols tx*4..tx*4+3)
    float mrow[4], lrow[4];
#pragma unroll
    for (int i = 0; i < 4; i++) {
        mrow[i] = __int_as_float(0xff800000);
        lrow[i] = 0.f;
        o2[i][0] = 0ull; o2[i][1] = 0ull;
    }

    for (int kv0 = 0; kv0 < SS; kv0 += 64) {
        __syncthreads();   // prev PV done with Ps/Vs; also orders Q stores (1st iter)
        {
            int r = t >> 2, cq0 = t & 3;
            const float* kb = g_k + ((size_t)head * SS + kv0 + r) * HD;
            const float* vb = g_v + ((size_t)head * SS + kv0 + r) * HD;
#pragma unroll
            for (int i = 0; i < 4; i++) {
                int hq = cq0 + 4 * i;
                float4 kv4 = *(const float4*)(kb + hq * 4);
#pragma unroll
                for (int j = 0; j < 4; j++)
                    KsT[(hq * 4 + j) * 64 + r] = ((const float*)&kv4)[j];
                *(float4*)&Vs[r * 64 + hq * 4] = *(const float4*)(vb + hq * 4);
            }
        }
        __syncthreads();

        // S = QK^T: sc2[i][jp] pairs over cols tx*4+2jp, +1
        u64 sc2[4][2];
#pragma unroll
        for (int i = 0; i < 4; i++) { sc2[i][0] = 0ull; sc2[i][1] = 0ull; }
        {
            const float* qr = QsT + ty * 4;
            const float* kr = KsT + tx * 4;
#pragma unroll 1
            for (int h0 = 0; h0 < 4; h0++) {
#pragma unroll
                for (int u = 0; u < 16; u++) {
                    float4 a4 = *(const float4*)(qr + u * 64);
                    float4 b4 = *(const float4*)(kr + u * 64);
                    u64 bp0 = ((const u64*)&b4)[0];
                    u64 bp1 = ((const u64*)&b4)[1];
                    const float* av = (const float*)&a4;
#pragma unroll
                    for (int i = 0; i < 4; i++) {
                        u64 ad = pk2(av[i], av[i]);
                        sc2[i][0] = fma2(ad, bp0, sc2[i][0]);
                        sc2[i][1] = fma2(ad, bp1, sc2[i][1]);
                    }
                }
                qr += 1024; kr += 1024;
            }
        }

        // unpack scores
        float sc[4][4];
#pragma unroll
        for (int i = 0; i < 4; i++) {
            upk2(sc2[i][0], sc[i][0], sc[i][1]);
            upk2(sc2[i][1], sc[i][2], sc[i][3]);
        }

        // online softmax (rows spread across 16 tx lanes; xor 1..8 stays in half-warp)
#pragma unroll
        for (int i = 0; i < 4; i++) {
            float mx = fmaxf(fmaxf(sc[i][0], sc[i][1]), fmaxf(sc[i][2], sc[i][3]));
#pragma unroll
            for (int off = 1; off < 16; off <<= 1)
                mx = fmaxf(mx, __shfl_xor_sync(0xffffffffu, mx, off));
            float mnew = fmaxf(mrow[i], mx);
            float ps = 0.f;
#pragma unroll
            for (int j = 0; j < 4; j++) {
                sc[i][j] = __expf(sc[i][j] - mnew);
                ps += sc[i][j];
            }
#pragma unroll
            for (int off = 1; off < 16; off <<= 1)
                ps += __shfl_xor_sync(0xffffffffu, ps, off);
            float alpha = __expf(mrow[i] - mnew);
            lrow[i] = lrow[i] * alpha + ps;
            mrow[i] = mnew;
            u64 al2 = pk2(alpha, alpha);
            o2[i][0] = mul2(o2[i][0], al2);
            o2[i][1] = mul2(o2[i][1], al2);
        }

        __syncthreads();   // all KsT reads done
        // P into KsT buffer as Ps[r][kv]
#pragma unroll
        for (int i = 0; i < 4; i++)
            *(float4*)&KsT[(ty * 4 + i) * 64 + tx * 4] =
                make_float4(sc[i][0], sc[i][1], sc[i][2], sc[i][3]);
        __syncthreads();

        // O += P @ V  (4 kv per step)
        {
            const float* pr = KsT + ty * 4 * 64;   // row base for i=0
            const float* vr = Vs + tx * 4;
#pragma unroll
            for (int kq = 0; kq < 16; kq++) {
                float4 a4[4];
                u64 bp[4][2];
#pragma unroll
                for (int i = 0; i < 4; i++)
                    a4[i] = *(const float4*)(pr + i * 64 + kq * 4);
#pragma unroll
                for (int k = 0; k < 4; k++) {
                    float4 b4 = *(const float4*)(vr + (kq * 4 + k) * 64);
                    bp[k][0] = ((const u64*)&b4)[0];
                    bp[k][1] = ((const u64*)&b4)[1];
                }
#pragma unroll
                for (int i = 0; i < 4; i++) {
                    const float* av = (const float*)&a4[i];
#pragma unroll
                    for (int k = 0; k < 4; k++) {
                        u64 ad = pk2(av[k], av[k]);
                        o2[i][0] = fma2(ad, bp[k][0], o2[i][0]);
                        o2[i][1] = fma2(ad, bp[k][1], o2[i][1]);
                    }
                }
            }
        }
    }

    // write attn output into g_A2 cols [0,768): rows m = s*B+b
    int b  = head / HH, hh = head - b * HH;
#pragma unroll
    for (int i = 0; i < 4; i++) {
        float inv = 1.f / lrow[i];
        int s = q0 + ty * 4 + i;
        float c0, c1, c2, c3;
        upk2(o2[i][0], c0, c1);
        upk2(o2[i][1], c2, c3);
        *(float4*)&g_A2[(size_t)(s * BB + b) * KA + hh * HD + tx * 4] =
            make_float4(c0 * inv, c1 * inv, c2 * inv, c3 * inv);
    }
}

// ---------------- launch ----------------
extern "C" void kernel_launch(void* const* d_in, const int* in_sizes, int n_in,
                              void* d_out, int out_size) {
    const float* query   = (const float*)d_in[0];
    // d_in[1] key, d_in[2] value: unused by reference (self-attn on query)
    const float* ipw     = (const float*)d_in[3];
    const float* ipb     = (const float*)d_in[4];
    const float* sc1     = (const float*)d_in[5];
    const float* sh1     = (const float*)d_in[6];
    const float* l1dw    = (const float*)d_in[7];
    const float* l1db    = (const float*)d_in[8];
    const float* l1uw    = (const float*)d_in[9];
    const float* l1ub    = (const float*)d_in[10];
    const float* l1s     = (const float*)d_in[11];
    const float* outw    = (const float*)d_in[12];
    const float* outb    = (const float*)d_in[13];
    const float* sc2     = (const float*)d_in[14];
    const float* sh2     = (const float*)d_in[15];
    const float* l2dw    = (const float*)d_in[16];
    const float* l2db    = (const float*)d_in[17];
    const float* l2uw    = (const float*)d_in[18];
    const float* l2ub    = (const float*)d_in[19];
    const float* l2s     = (const float*)d_in[20];
    float* out = (float*)d_out;

    // order chosen so the ncu sample (observed to land on the 4th launch)
    // catches gemm128<2> (qkv) — the tcgen05 candidate.
    pack_query_kernel<<<(MM * DD / 4 + 255) / 256, 256>>>(query);                     // 0
    gemm64_kernel<1><<<dim3(1, MM / 32), 256>>>(query, l1dw, l1db);                   // 1
    prep_wqkv_kernel<<<(E3 * KA + 255) / 256, 256>>>(ipw, ipb, sc1, sh1, l1uw, l1ub, l1s); // 2
    gemm128_kernel<2><<<dim3(E3 / 128, MM / 128), 256>>>(nullptr);                    // 3
    attn_kernel<<<dim3(NHEAD, SS / 64), 256>>>();                                     // 4
    gemm64_kernel<3><<<dim3(1, MM / 32), 256>>>(nullptr, l2dw, l2db);                 // 5
    prep_wout_kernel<<<(DD * KA + 255) / 256, 256>>>(outw, outb, sc2, sh2, l2uw, l2ub, l2s); // 6
    gemm128_kernel<0><<<dim3(DD / 128, MM / 128), 256>>>(out);                        // 7
}

// round 10
// speedup vs baseline: 1.1607x; 1.1607x over previous
#include <cuda_runtime.h>
#include <cuda_bf16.h>
#include <cstdint>

#define SS 2048
#define BB 2
#define DD 768
#define HH 12
#define HD 64
#define RR 64
#define E3 (3*DD)        // 2304
#define MM (SS*BB)       // 4096
#define KA (DD+RR)       // 832
#define NHEAD (BB*HH)    // 24

// ================= base-PTX tensor helpers (compute_103-safe) =================
__device__ __forceinline__ uint32_t smem_u32(const void* p) {
    uint32_t a;
    asm("{ .reg .u64 t; cvta.to.shared.u64 t, %1; cvt.u32.u64 %0, t; }" : "=r"(a) : "l"(p));
    return a;
}
__device__ __forceinline__ void ldsm4(uint32_t* r, uint32_t a) {
    asm volatile("ldmatrix.sync.aligned.m8n8.x4.shared.b16 {%0,%1,%2,%3}, [%4];"
                 : "=r"(r[0]), "=r"(r[1]), "=r"(r[2]), "=r"(r[3]) : "r"(a));
}
__device__ __forceinline__ void ldsm2(uint32_t* r, uint32_t a) {
    asm volatile("ldmatrix.sync.aligned.m8n8.x2.shared.b16 {%0,%1}, [%2];"
                 : "=r"(r[0]), "=r"(r[1]) : "r"(a));
}
__device__ __forceinline__ void mma16816(float* d, const uint32_t* a, const uint32_t* b) {
    asm volatile(
        "mma.sync.aligned.m16n8k16.row.col.f32.bf16.bf16.f32 "
        "{%0,%1,%2,%3}, {%4,%5,%6,%7}, {%8,%9}, {%0,%1,%2,%3};"
        : "+f"(d[0]), "+f"(d[1]), "+f"(d[2]), "+f"(d[3])
        : "r"(a[0]), "r"(a[1]), "r"(a[2]), "r"(a[3]), "r"(b[0]), "r"(b[1]));
}

// bf16 hi/lo split
__device__ __forceinline__ void split_bf16(float x, __nv_bfloat16& h, __nv_bfloat16& l) {
    h = __float2bfloat16(x);
    l = __float2bfloat16(x - __bfloat162float(h));
}

// ================= device scratch =================
__device__ __align__(16) __nv_bfloat16 g_A1h[MM*KA], g_A1l[MM*KA];  // [query | relu(lora1)]
__device__ __align__(16) __nv_bfloat16 g_A2h[MM*KA], g_A2l[MM*KA];  // [attn_out | relu(lora2)]
__device__ __align__(16) float g_A2[MM*KA];                          // fp32 attn out (lora2 input)
__device__ __align__(16) __nv_bfloat16 g_Wqh[E3*KA], g_Wql[E3*KA];
__device__ __align__(16) __nv_bfloat16 g_Woh[DD*KA], g_Wol[DD*KA];
__device__ float g_bqkv[E3];
__device__ float g_bout[DD];
__device__ __align__(16) float g_q[NHEAD*SS*HD];   // pre-scaled by hd^-0.5
__device__ __align__(16) float g_k[NHEAD*SS*HD];
__device__ __align__(16) float g_v[NHEAD*SS*HD];

// ================= weight prep (fp32 -> bf16 hi/lo) =================
__global__ void prep_wqkv_kernel(const float* __restrict__ W, const float* __restrict__ b,
                                 const float* __restrict__ sc, const float* __restrict__ sh,
                                 const float* __restrict__ uw, const float* __restrict__ ub,
                                 const float* __restrict__ ls) {
    int idx = blockIdx.x * 256 + threadIdx.x;
    if (idx >= E3 * KA) return;
    int n = idx / KA, k = idx - n * KA;
    float l = ls[0];
    float v = (k < DD) ? W[n * DD + k] * sc[n] : uw[n * RR + (k - DD)] * l;
    __nv_bfloat16 h, lo; split_bf16(v, h, lo);
    g_Wqh[idx] = h; g_Wql[idx] = lo;
    if (k == 0) g_bqkv[n] = b[n] * sc[n] + sh[n] + ub[n] * l;
}

__global__ void prep_wout_kernel(const float* __restrict__ W, const float* __restrict__ b,
                                 const float* __restrict__ sc, const float* __restrict__ sh,
                                 const float* __restrict__ uw, const float* __restrict__ ub,
                                 const float* __restrict__ ls) {
    int idx = blockIdx.x * 256 + threadIdx.x;
    if (idx >= DD * KA) return;
    int n = idx / KA, k = idx - n * KA;
    float l = ls[0];
    float v = (k < DD) ? W[n * DD + k] * sc[n] : uw[n * RR + (k - DD)] * l;
    __nv_bfloat16 h, lo; split_bf16(v, h, lo);
    g_Woh[idx] = h; g_Wol[idx] = lo;
    if (k == 0) g_bout[n] = b[n] * sc[n] + sh[n] + ub[n] * l;
}

__global__ void pack_query_kernel(const float* __restrict__ q) {
    int idx = blockIdx.x * 256 + threadIdx.x;      // float4 index
    if (idx >= MM * DD / 4) return;
    int m = idx / (DD / 4), d4 = idx - m * (DD / 4);
    float4 v = *(const float4*)(q + (size_t)m * DD + d4 * 4);
    size_t o = (size_t)m * KA + d4 * 4;
    __nv_bfloat16 h0,l0,h1,l1,h2,l2,h3,l3;
    split_bf16(v.x, h0, l0); split_bf16(v.y, h1, l1);
    split_bf16(v.z, h2, l2); split_bf16(v.w, h3, l3);
    *(__nv_bfloat162*)&g_A1h[o]     = __nv_bfloat162{h0, h1};
    *(__nv_bfloat162*)&g_A1h[o + 2] = __nv_bfloat162{h2, h3};
    *(__nv_bfloat162*)&g_A1l[o]     = __nv_bfloat162{l0, l1};
    *(__nv_bfloat162*)&g_A1l[o + 2] = __nv_bfloat162{l2, l3};
}

// ================= lora-down GEMM: 32x64 tiles (SIMT fp32) =================
// MODE 1: A=arg(query, lda 768) -> relu -> bf16 hi/lo into g_A1h/l[:,768:]
// MODE 3: A=g_A2 (lda KA)       -> relu -> bf16 hi/lo into g_A2h/l[:,768:]
template<int MODE>
__global__ __launch_bounds__(256) void gemm64_kernel(
    const float* __restrict__ Aarg,
    const float* __restrict__ Warg,
    const float* __restrict__ barg)
{
    const float* A = (MODE == 1) ? Aarg : g_A2;
    const int lda  = (MODE == 1) ? DD : KA;
    const float* W = Warg; const float* bias = barg;

    __shared__ float As[16][33];
    __shared__ float Bs[16][65];
    int t  = threadIdx.x;
    int tx = t & 15, ty = t >> 4;
    int m0 = blockIdx.y * 32;
    int ar = t >> 4, ak = t & 15;

    float acc[2][4];
#pragma unroll
    for (int i = 0; i < 2; i++)
#pragma unroll
        for (int j = 0; j < 4; j++) acc[i][j] = 0.f;

    for (int k0 = 0; k0 < DD; k0 += 16) {
        As[ak][ar]      = A[(size_t)(m0 + ar) * lda + k0 + ak];
        As[ak][ar + 16] = A[(size_t)(m0 + ar + 16) * lda + k0 + ak];
#pragma unroll
        for (int p = 0; p < 4; p++)
            Bs[ak][ar + 16 * p] = W[(size_t)(ar + 16 * p) * DD + k0 + ak];
        __syncthreads();
#pragma unroll
        for (int kk = 0; kk < 16; kk++) {
            float a0 = As[kk][ty], a1 = As[kk][ty + 16];
            float bf[4];
#pragma unroll
            for (int j = 0; j < 4; j++) bf[j] = Bs[kk][tx + 16 * j];
#pragma unroll
            for (int j = 0; j < 4; j++) {
                acc[0][j] = fmaf(a0, bf[j], acc[0][j]);
                acc[1][j] = fmaf(a1, bf[j], acc[1][j]);
            }
        }
        __syncthreads();
    }

#pragma unroll
    for (int i = 0; i < 2; i++) {
        int m = m0 + ty + 16 * i;
#pragma unroll
        for (int j = 0; j < 4; j++) {
            int n = tx + 16 * j;
            float v = fmaxf(acc[i][j] + bias[n], 0.f);
            __nv_bfloat16 h, l; split_bf16(v, h, l);
            size_t o = (size_t)m * KA + DD + n;
            if (MODE == 1) { g_A1h[o] = h; g_A1l[o] = l; }
            else           { g_A2h[o] = h; g_A2l[o] = l; }
        }
    }
}

// ================= mma.sync GEMM: 128x128, 3 bf16-split passes over K=832 ====
// acc = Ahi*Bhi + Alo*Bhi + Ahi*Blo  (fp32 accumulators in registers)
// MODE 2: A=g_A1h/l, B=g_Wqh/l, bias=g_bqkv -> scatter g_q/g_k/g_v
// MODE 0: A=g_A2h/l, B=g_Woh/l, bias=g_bout -> Carg (d_out, ld 768)
template<int MODE>
__global__ __launch_bounds__(256) void gemm_mma_kernel(float* __restrict__ Carg)
{
    const __nv_bfloat16* Ah = (MODE == 2) ? g_A1h : g_A2h;
    const __nv_bfloat16* Al = (MODE == 2) ? g_A1l : g_A2l;
    const __nv_bfloat16* Bh = (MODE == 2) ? g_Wqh : g_Woh;
    const __nv_bfloat16* Bl = (MODE == 2) ? g_Wql : g_Wol;
    const float* bias       = (MODE == 2) ? g_bqkv : g_bout;

    __shared__ __align__(16) __nv_bfloat16 sA[2][128 * 32];
    __shared__ __align__(16) __nv_bfloat16 sB[2][128 * 32];

    const int t = threadIdx.x, lane = t & 31, wid = t >> 5;
    const int m0 = blockIdx.y * 128, n0 = blockIdx.x * 128;
    const int wm = (wid & 1) * 64, wn = (wid >> 1) * 32;

    // ---- loader: thread covers row t>>1, 16-bf16 half t&1 (32B = 2 uint4) ----
    const int lrow = t >> 1, lhalf = t & 1;
    // smem chunk swizzle: phys16B = chunk ^ ((row>>1)&3)
    const int so0 = lrow * 32 + (((lhalf * 2)     ^ ((lrow >> 1) & 3)) * 8);
    const int so1 = lrow * 32 + (((lhalf * 2 + 1) ^ ((lrow >> 1) & 3)) * 8);

    const int CH  = KA / 32;       // 26 chunks per pass
    const int TOT = 3 * CH;        // 78

    const size_t arow = (size_t)(m0 + lrow) * KA + lhalf * 16;
    const size_t brow = (size_t)(n0 + lrow) * KA + lhalf * 16;

    uint4 ra0, ra1, rb0, rb1;
    {
        const __nv_bfloat16* pa = Ah + arow;
        const __nv_bfloat16* pb = Bh + brow;
        ra0 = *(const uint4*)pa; ra1 = *(const uint4*)(pa + 8);
        rb0 = *(const uint4*)pb; rb1 = *(const uint4*)(pb + 8);
    }

    float acc[4][4][4];
#pragma unroll
    for (int i = 0; i < 4; i++)
#pragma unroll
        for (int j = 0; j < 4; j++)
#pragma unroll
            for (int k = 0; k < 4; k++) acc[i][j][k] = 0.f;

    // ldmatrix byte offsets (lane-dependent, chunk-invariant)
    uint32_t aoff[2][4], boff[2][4];
    {
        int g = lane >> 3, lr = lane & 7;
#pragma unroll
        for (int kk = 0; kk < 2; kk++)
#pragma unroll
            for (int fi = 0; fi < 4; fi++) {
                int row = wm + fi * 16 + (g & 1) * 8 + lr;
                int ch  = (kk * 2 + (g >> 1)) ^ ((row >> 1) & 3);
                aoff[kk][fi] = (uint32_t)(row * 32 + ch * 8) * 2;
            }
        int g2 = (lane >> 3) & 1;
#pragma unroll
        for (int kk = 0; kk < 2; kk++)
#pragma unroll
            for (int fj = 0; fj < 4; fj++) {
                int row = wn + fj * 8 + lr;
                int ch  = (kk * 2 + g2) ^ ((row >> 1) & 3);
                boff[kk][fj] = (uint32_t)(row * 32 + ch * 8) * 2;
            }
    }
    const uint32_t sAb[2] = { smem_u32(sA[0]), smem_u32(sA[1]) };
    const uint32_t sBb[2] = { smem_u32(sB[0]), smem_u32(sB[1]) };

    // store chunk 0 into buffer 0
    *(uint4*)(sA[0] + so0) = ra0; *(uint4*)(sA[0] + so1) = ra1;
    *(uint4*)(sB[0] + so0) = rb0; *(uint4*)(sB[0] + so1) = rb1;
    __syncthreads();

    for (int c = 0; c < TOT; c++) {
        int cur = c & 1;
        if (c + 1 < TOT) {
            int c1 = c + 1, p = c1 / CH, kc = (c1 - p * CH) * 32;
            const __nv_bfloat16* pa = ((p == 1) ? Al : Ah) + arow + kc;
            const __nv_bfloat16* pb = ((p == 2) ? Bl : Bh) + brow + kc;
            ra0 = *(const uint4*)pa; ra1 = *(const uint4*)(pa + 8);
            rb0 = *(const uint4*)pb; rb1 = *(const uint4*)(pb + 8);
        }
#pragma unroll
        for (int kk = 0; kk < 2; kk++) {
            uint32_t af[4][4], bf[4][2];
#pragma unroll
            for (int fi = 0; fi < 4; fi++) ldsm4(af[fi], sAb[cur] + aoff[kk][fi]);
#pragma unroll
            for (int fj = 0; fj < 4; fj++) ldsm2(bf[fj], sBb[cur] + boff[kk][fj]);
#pragma unroll
            for (int fi = 0; fi < 4; fi++)
#pragma unroll
                for (int fj = 0; fj < 4; fj++)
                    mma16816(acc[fi][fj], af[fi], bf[fj]);
        }
        if (c + 1 < TOT) {
            int nxt = cur ^ 1;
            *(uint4*)(sA[nxt] + so0) = ra0; *(uint4*)(sA[nxt] + so1) = ra1;
            *(uint4*)(sB[nxt] + so0) = rb0; *(uint4*)(sB[nxt] + so1) = rb1;
            __syncthreads();
        }
    }

    // ---- epilogue: lane holds (row cr / cr+8, cols cc2, cc2+1) per frag ----
    const int cr = lane >> 2, cc2 = (lane & 3) * 2;
    if (MODE == 0) {
#pragma unroll
        for (int fi = 0; fi < 4; fi++) {
            int r0 = m0 + wm + fi * 16 + cr;
#pragma unroll
            for (int fj = 0; fj < 4; fj++) {
                int nf = n0 + wn + fj * 8 + cc2;
                float b0 = bias[nf], b1 = bias[nf + 1];
                *(float2*)(Carg + (size_t)r0 * DD + nf) =
                    make_float2(acc[fi][fj][0] + b0, acc[fi][fj][1] + b1);
                *(float2*)(Carg + (size_t)(r0 + 8) * DD + nf) =
                    make_float2(acc[fi][fj][2] + b0, acc[fi][fj][3] + b1);
            }
        }
    } else {
        int part = n0 / DD;                 // 768 = 6*128: block never crosses
        float* dst = (part == 0) ? g_q : (part == 1) ? g_k : g_v;
        float scl  = (part == 0) ? 0.125f : 1.f;   // hd^-0.5 on q
#pragma unroll
        for (int fi = 0; fi < 4; fi++) {
            int r0 = m0 + wm + fi * 16 + cr;
            int s0 = r0 >> 1, bi0 = r0 & 1;
            int r1 = r0 + 8;
            int s1 = r1 >> 1, bi1 = r1 & 1;
#pragma unroll
            for (int fj = 0; fj < 4; fj++) {
                int nf = n0 + wn + fj * 8 + cc2;
                float b0 = bias[nf], b1 = bias[nf + 1];
                int nip = nf - part * DD;
                int h = nip >> 6, ccn = nip & 63;
                *(float2*)(dst + ((size_t)(bi0 * HH + h) * SS + s0) * HD + ccn) =
                    make_float2((acc[fi][fj][0] + b0) * scl, (acc[fi][fj][1] + b1) * scl);
                *(float2*)(dst + ((size_t)(bi1 * HH + h) * SS + s1) * HD + ccn) =
                    make_float2((acc[fi][fj][2] + b0) * scl, (acc[fi][fj][3] + b1) * scl);
            }
        }
    }
}

// ================= flash attention (SIMT fp32, R6-proven version) ============
__global__ __launch_bounds__(256) void attn_kernel() {
    __shared__ float QsT[64 * 64];   // [h][r]
    __shared__ float KsT[64 * 64];   // [h][c]; reused as P [r][kv]
    __shared__ float Vs[64 * 64];    // [kv][c]

    int head = blockIdx.x;
    int q0   = blockIdx.y * 64;
    int t  = threadIdx.x;
    int tx = t & 15, ty = t >> 4;

    {
        int r = t >> 2, cq0 = t & 3;
        const float* qb = g_q + ((size_t)head * SS + q0 + r) * HD;
#pragma unroll
        for (int i = 0; i < 4; i++) {
            int hq = cq0 + 4 * i;
            float4 v = *(const float4*)(qb + hq * 4);
#pragma unroll
            for (int j = 0; j < 4; j++)
                QsT[(hq * 4 + j) * 64 + r] = ((const float*)&v)[j];
        }
    }

    float o[4][4], mrow[4], lrow[4];
#pragma unroll
    for (int i = 0; i < 4; i++) {
        mrow[i] = __int_as_float(0xff800000);
        lrow[i] = 0.f;
#pragma unroll
        for (int j = 0; j < 4; j++) o[i][j] = 0.f;
    }

    for (int kv0 = 0; kv0 < SS; kv0 += 64) {
        __syncthreads();
        {
            int r = t >> 2, cq0 = t & 3;
            const float* kb = g_k + ((size_t)head * SS + kv0 + r) * HD;
            const float* vb = g_v + ((size_t)head * SS + kv0 + r) * HD;
#pragma unroll
            for (int i = 0; i < 4; i++) {
                int hq = cq0 + 4 * i;
                float4 kv4 = *(const float4*)(kb + hq * 4);
#pragma unroll
                for (int j = 0; j < 4; j++)
                    KsT[(hq * 4 + j) * 64 + r] = ((const float*)&kv4)[j];
                *(float4*)&Vs[r * 64 + hq * 4] = *(const float4*)(vb + hq * 4);
            }
        }
        __syncthreads();

        float sc[4][4];
#pragma unroll
        for (int i = 0; i < 4; i++)
#pragma unroll
            for (int j = 0; j < 4; j++) sc[i][j] = 0.f;
        {
            const float* qr = QsT + ty * 4;
            const float* kr = KsT + tx * 4;
#pragma unroll 1
            for (int h0 = 0; h0 < 4; h0++) {
#pragma unroll
                for (int u = 0; u < 16; u++) {
                    float4 a4 = *(const float4*)(qr + u * 64);
                    float4 b4 = *(const float4*)(kr + u * 64);
                    const float* av = (const float*)&a4;
                    const float* bv = (const float*)&b4;
#pragma unroll
                    for (int i = 0; i < 4; i++)
#pragma unroll
                        for (int j = 0; j < 4; j++)
                            sc[i][j] = fmaf(av[i], bv[j], sc[i][j]);
                }
                qr += 1024; kr += 1024;
            }
        }

#pragma unroll
        for (int i = 0; i < 4; i++) {
            float mx = fmaxf(fmaxf(sc[i][0], sc[i][1]), fmaxf(sc[i][2], sc[i][3]));
#pragma unroll
            for (int off = 1; off < 16; off <<= 1)
                mx = fmaxf(mx, __shfl_xor_sync(0xffffffffu, mx, off));
            float mnew = fmaxf(mrow[i], mx);
            float ps = 0.f;
#pragma unroll
            for (int j = 0; j < 4; j++) {
                sc[i][j] = __expf(sc[i][j] - mnew);
                ps += sc[i][j];
            }
#pragma unroll
            for (int off = 1; off < 16; off <<= 1)
                ps += __shfl_xor_sync(0xffffffffu, ps, off);
            float alpha = __expf(mrow[i] - mnew);
            lrow[i] = lrow[i] * alpha + ps;
            mrow[i] = mnew;
#pragma unroll
            for (int j = 0; j < 4; j++) o[i][j] *= alpha;
        }

        __syncthreads();
#pragma unroll
        for (int i = 0; i < 4; i++)
            *(float4*)&KsT[(ty * 4 + i) * 64 + tx * 4] =
                make_float4(sc[i][0], sc[i][1], sc[i][2], sc[i][3]);
        __syncthreads();

        {
            const float* pr = KsT + ty * 4 * 64;
            const float* vr = Vs + tx * 4;
#pragma unroll
            for (int kq = 0; kq < 16; kq++) {
                float4 a4[4], b4[4];
#pragma unroll
                for (int i = 0; i < 4; i++)
                    a4[i] = *(const float4*)(pr + i * 64 + kq * 4);
#pragma unroll
                for (int k = 0; k < 4; k++)
                    b4[k] = *(const float4*)(vr + (kq * 4 + k) * 64);
#pragma unroll
                for (int i = 0; i < 4; i++) {
                    const float* av = (const float*)&a4[i];
#pragma unroll
                    for (int k = 0; k < 4; k++) {
                        const float* bv = (const float*)&b4[k];
#pragma unroll
                        for (int j = 0; j < 4; j++)
                            o[i][j] = fmaf(av[k], bv[j], o[i][j]);
                    }
                }
            }
        }
    }

    // write attn out: fp32 (lora2 input) + bf16 hi/lo (out-proj MMA input)
    int b  = head / HH, hh = head - b * HH;
#pragma unroll
    for (int i = 0; i < 4; i++) {
        float inv = 1.f / lrow[i];
        int s = q0 + ty * 4 + i;
        size_t ob = (size_t)(s * BB + b) * KA + hh * HD + tx * 4;
        float4 v = make_float4(o[i][0] * inv, o[i][1] * inv, o[i][2] * inv, o[i][3] * inv);
        *(float4*)&g_A2[ob] = v;
        __nv_bfloat16 h0,l0,h1,l1,h2,l2,h3,l3;
        split_bf16(v.x, h0, l0); split_bf16(v.y, h1, l1);
        split_bf16(v.z, h2, l2); split_bf16(v.w, h3, l3);
        *(__nv_bfloat162*)&g_A2h[ob]     = __nv_bfloat162{h0, h1};
        *(__nv_bfloat162*)&g_A2h[ob + 2] = __nv_bfloat162{h2, h3};
        *(__nv_bfloat162*)&g_A2l[ob]     = __nv_bfloat162{l0, l1};
        *(__nv_bfloat162*)&g_A2l[ob + 2] = __nv_bfloat162{l2, l3};
    }
}

// ================= launch =================
extern "C" void kernel_launch(void* const* d_in, const int* in_sizes, int n_in,
                              void* d_out, int out_size) {
    const float* query   = (const float*)d_in[0];
    // d_in[1] key, d_in[2] value: unused by reference (self-attn on query)
    const float* ipw     = (const float*)d_in[3];
    const float* ipb     = (const float*)d_in[4];
    const float* sc1     = (const float*)d_in[5];
    const float* sh1     = (const float*)d_in[6];
    const float* l1dw    = (const float*)d_in[7];
    const float* l1db    = (const float*)d_in[8];
    const float* l1uw    = (const float*)d_in[9];
    const float* l1ub    = (const float*)d_in[10];
    const float* l1s     = (const float*)d_in[11];
    const float* outw    = (const float*)d_in[12];
    const float* outb    = (const float*)d_in[13];
    const float* sc2     = (const float*)d_in[14];
    const float* sh2     = (const float*)d_in[15];
    const float* l2dw    = (const float*)d_in[16];
    const float* l2db    = (const float*)d_in[17];
    const float* l2uw    = (const float*)d_in[18];
    const float* l2ub    = (const float*)d_in[19];
    const float* l2s     = (const float*)d_in[20];
    float* out = (float*)d_out;

    pack_query_kernel<<<(MM * DD / 4 + 255) / 256, 256>>>(query);
    gemm64_kernel<1><<<dim3(1, MM / 32), 256>>>(query, l1dw, l1db);
    prep_wqkv_kernel<<<(E3 * KA + 255) / 256, 256>>>(ipw, ipb, sc1, sh1, l1uw, l1ub, l1s);
    gemm_mma_kernel<2><<<dim3(E3 / 128, MM / 128), 256>>>(nullptr);
    attn_kernel<<<dim3(NHEAD, SS / 64), 256>>>();
    gemm64_kernel<3><<<dim3(1, MM / 32), 256>>>(nullptr, l2dw, l2db);
    prep_wout_kernel<<<(DD * KA + 255) / 256, 256>>>(outw, outb, sc2, sh2, l2uw, l2ub, l2s);
    gemm_mma_kernel<0><<<dim3(DD / 128, MM / 128), 256>>>(out);
}

// round 17
// speedup vs baseline: 1.7772x; 1.5311x over previous
#include <cuda_runtime.h>
#include <cuda_bf16.h>
#include <cstdint>

#define SS 2048
#define BB 2
#define DD 768
#define HH 12
#define HD 64
#define RR 64
#define E3 (3*DD)        // 2304
#define MM (SS*BB)       // 4096
#define KA (DD+RR)       // 832
#define NHEAD (BB*HH)    // 24

// ================= base-PTX tensor helpers (compute_103-safe) =================
__device__ __forceinline__ uint32_t smem_u32(const void* p) {
    uint32_t a;
    asm("{ .reg .u64 t; cvta.to.shared.u64 t, %1; cvt.u32.u64 %0, t; }" : "=r"(a) : "l"(p));
    return a;
}
__device__ __forceinline__ void ldsm4(uint32_t* r, uint32_t a) {
    asm volatile("ldmatrix.sync.aligned.m8n8.x4.shared.b16 {%0,%1,%2,%3}, [%4];"
                 : "=r"(r[0]), "=r"(r[1]), "=r"(r[2]), "=r"(r[3]) : "r"(a));
}
__device__ __forceinline__ void ldsm2(uint32_t* r, uint32_t a) {
    asm volatile("ldmatrix.sync.aligned.m8n8.x2.shared.b16 {%0,%1}, [%2];"
                 : "=r"(r[0]), "=r"(r[1]) : "r"(a));
}
__device__ __forceinline__ void ldsm2t(uint32_t* r, uint32_t a) {
    asm volatile("ldmatrix.sync.aligned.m8n8.x2.trans.shared.b16 {%0,%1}, [%2];"
                 : "=r"(r[0]), "=r"(r[1]) : "r"(a));
}
__device__ __forceinline__ void mma16816(float* d, const uint32_t* a, const uint32_t* b) {
    asm volatile(
        "mma.sync.aligned.m16n8k16.row.col.f32.bf16.bf16.f32 "
        "{%0,%1,%2,%3}, {%4,%5,%6,%7}, {%8,%9}, {%0,%1,%2,%3};"
        : "+f"(d[0]), "+f"(d[1]), "+f"(d[2]), "+f"(d[3])
        : "r"(a[0]), "r"(a[1]), "r"(a[2]), "r"(a[3]), "r"(b[0]), "r"(b[1]));
}

// bf16 hi/lo split
__device__ __forceinline__ void split_bf16(float x, __nv_bfloat16& h, __nv_bfloat16& l) {
    h = __float2bfloat16(x);
    l = __float2bfloat16(x - __bfloat162float(h));
}
__device__ __forceinline__ void split2(float x, float y, uint32_t& hi, uint32_t& lo) {
    __nv_bfloat16 hx, lx, hy, ly;
    split_bf16(x, hx, lx); split_bf16(y, hy, ly);
    __nv_bfloat162 vh{hx, hy}, vl{lx, ly};
    hi = *(uint32_t*)&vh; lo = *(uint32_t*)&vl;
}

// ================= device scratch =================
__device__ __align__(16) __nv_bfloat16 g_A1h[MM*KA], g_A1l[MM*KA];  // [query | relu(lora1)]
__device__ __align__(16) __nv_bfloat16 g_A2h[MM*KA], g_A2l[MM*KA];  // [attn_out | relu(lora2)]
__device__ __align__(16) float g_A2[MM*KA];                          // fp32 attn out (lora2 input)
__device__ __align__(16) __nv_bfloat16 g_Wqh[E3*KA], g_Wql[E3*KA];
__device__ __align__(16) __nv_bfloat16 g_Woh[DD*KA], g_Wol[DD*KA];
__device__ float g_bqkv[E3];
__device__ float g_bout[DD];
// q/k/v in bf16 hi/lo, [B*H][S][hd]; q pre-scaled by hd^-0.5
__device__ __align__(16) __nv_bfloat16 g_qh[NHEAD*SS*HD], g_ql[NHEAD*SS*HD];
__device__ __align__(16) __nv_bfloat16 g_kh[NHEAD*SS*HD], g_kl[NHEAD*SS*HD];
__device__ __align__(16) __nv_bfloat16 g_vh[NHEAD*SS*HD], g_vl[NHEAD*SS*HD];

// ================= weight prep (fp32 -> bf16 hi/lo) =================
__global__ void prep_wqkv_kernel(const float* __restrict__ W, const float* __restrict__ b,
                                 const float* __restrict__ sc, const float* __restrict__ sh,
                                 const float* __restrict__ uw, const float* __restrict__ ub,
                                 const float* __restrict__ ls) {
    int idx = blockIdx.x * 256 + threadIdx.x;
    if (idx >= E3 * KA) return;
    int n = idx / KA, k = idx - n * KA;
    float l = ls[0];
    float v = (k < DD) ? W[n * DD + k] * sc[n] : uw[n * RR + (k - DD)] * l;
    __nv_bfloat16 h, lo; split_bf16(v, h, lo);
    g_Wqh[idx] = h; g_Wql[idx] = lo;
    if (k == 0) g_bqkv[n] = b[n] * sc[n] + sh[n] + ub[n] * l;
}

__global__ void prep_wout_kernel(const float* __restrict__ W, const float* __restrict__ b,
                                 const float* __restrict__ sc, const float* __restrict__ sh,
                                 const float* __restrict__ uw, const float* __restrict__ ub,
                                 const float* __restrict__ ls) {
    int idx = blockIdx.x * 256 + threadIdx.x;
    if (idx >= DD * KA) return;
    int n = idx / KA, k = idx - n * KA;
    float l = ls[0];
    float v = (k < DD) ? W[n * DD + k] * sc[n] : uw[n * RR + (k - DD)] * l;
    __nv_bfloat16 h, lo; split_bf16(v, h, lo);
    g_Woh[idx] = h; g_Wol[idx] = lo;
    if (k == 0) g_bout[n] = b[n] * sc[n] + sh[n] + ub[n] * l;
}

__global__ void pack_query_kernel(const float* __restrict__ q) {
    int idx = blockIdx.x * 256 + threadIdx.x;      // float4 index
    if (idx >= MM * DD / 4) return;
    int m = idx / (DD / 4), d4 = idx - m * (DD / 4);
    float4 v = *(const float4*)(q + (size_t)m * DD + d4 * 4);
    size_t o = (size_t)m * KA + d4 * 4;
    uint32_t h0, l0, h1, l1;
    split2(v.x, v.y, h0, l0); split2(v.z, v.w, h1, l1);
    *(uint32_t*)&g_A1h[o]     = h0; *(uint32_t*)&g_A1h[o + 2] = h1;
    *(uint32_t*)&g_A1l[o]     = l0; *(uint32_t*)&g_A1l[o + 2] = l1;
}

// ================= lora-down GEMM: 32x64 tiles (SIMT fp32) =================
// MODE 1: A=arg(query, lda 768) -> relu -> bf16 hi/lo into g_A1h/l[:,768:]
// MODE 3: A=g_A2 (lda KA)       -> relu -> bf16 hi/lo into g_A2h/l[:,768:]
template<int MODE>
__global__ __launch_bounds__(256) void gemm64_kernel(
    const float* __restrict__ Aarg,
    const float* __restrict__ Warg,
    const float* __restrict__ barg)
{
    const float* A = (MODE == 1) ? Aarg : g_A2;
    const int lda  = (MODE == 1) ? DD : KA;
    const float* W = Warg; const float* bias = barg;

    __shared__ float As[16][33];
    __shared__ float Bs[16][65];
    int t  = threadIdx.x;
    int tx = t & 15, ty = t >> 4;
    int m0 = blockIdx.y * 32;
    int ar = t >> 4, ak = t & 15;

    float acc[2][4];
#pragma unroll
    for (int i = 0; i < 2; i++)
#pragma unroll
        for (int j = 0; j < 4; j++) acc[i][j] = 0.f;

    for (int k0 = 0; k0 < DD; k0 += 16) {
        As[ak][ar]      = A[(size_t)(m0 + ar) * lda + k0 + ak];
        As[ak][ar + 16] = A[(size_t)(m0 + ar + 16) * lda + k0 + ak];
#pragma unroll
        for (int p = 0; p < 4; p++)
            Bs[ak][ar + 16 * p] = W[(size_t)(ar + 16 * p) * DD + k0 + ak];
        __syncthreads();
#pragma unroll
        for (int kk = 0; kk < 16; kk++) {
            float a0 = As[kk][ty], a1 = As[kk][ty + 16];
            float bf[4];
#pragma unroll
            for (int j = 0; j < 4; j++) bf[j] = Bs[kk][tx + 16 * j];
#pragma unroll
            for (int j = 0; j < 4; j++) {
                acc[0][j] = fmaf(a0, bf[j], acc[0][j]);
                acc[1][j] = fmaf(a1, bf[j], acc[1][j]);
            }
        }
        __syncthreads();
    }

#pragma unroll
    for (int i = 0; i < 2; i++) {
        int m = m0 + ty + 16 * i;
#pragma unroll
        for (int j = 0; j < 4; j++) {
            int n = tx + 16 * j;
            float v = fmaxf(acc[i][j] + bias[n], 0.f);
            __nv_bfloat16 h, l; split_bf16(v, h, l);
            size_t o = (size_t)m * KA + DD + n;
            if (MODE == 1) { g_A1h[o] = h; g_A1l[o] = l; }
            else           { g_A2h[o] = h; g_A2l[o] = l; }
        }
    }
}

// ================= mma.sync GEMM: 128x128, 3 bf16-split passes over K=832 ====
// acc = Ahi*Bhi + Alo*Bhi + Ahi*Blo  (fp32 accumulators in registers)
// MODE 2: A=g_A1h/l, B=g_Wqh/l, bias=g_bqkv -> scatter bf16 hi/lo q/k/v
// MODE 0: A=g_A2h/l, B=g_Woh/l, bias=g_bout -> Carg (d_out, ld 768)
template<int MODE>
__global__ __launch_bounds__(256) void gemm_mma_kernel(float* __restrict__ Carg)
{
    const __nv_bfloat16* Ah = (MODE == 2) ? g_A1h : g_A2h;
    const __nv_bfloat16* Al = (MODE == 2) ? g_A1l : g_A2l;
    const __nv_bfloat16* Bh = (MODE == 2) ? g_Wqh : g_Woh;
    const __nv_bfloat16* Bl = (MODE == 2) ? g_Wql : g_Wol;
    const float* bias       = (MODE == 2) ? g_bqkv : g_bout;

    __shared__ __align__(16) __nv_bfloat16 sA[2][128 * 32];
    __shared__ __align__(16) __nv_bfloat16 sB[2][128 * 32];

    const int t = threadIdx.x, lane = t & 31, wid = t >> 5;
    const int m0 = blockIdx.y * 128, n0 = blockIdx.x * 128;
    const int wm = (wid & 1) * 64, wn = (wid >> 1) * 32;

    const int lrow = t >> 1, lhalf = t & 1;
    const int so0 = lrow * 32 + (((lhalf * 2)     ^ ((lrow >> 1) & 3)) * 8);
    const int so1 = lrow * 32 + (((lhalf * 2 + 1) ^ ((lrow >> 1) & 3)) * 8);

    const int CH  = KA / 32;       // 26 chunks per pass
    const int TOT = 3 * CH;        // 78

    const size_t arow = (size_t)(m0 + lrow) * KA + lhalf * 16;
    const size_t brow = (size_t)(n0 + lrow) * KA + lhalf * 16;

    uint4 ra0, ra1, rb0, rb1;
    {
        const __nv_bfloat16* pa = Ah + arow;
        const __nv_bfloat16* pb = Bh + brow;
        ra0 = *(const uint4*)pa; ra1 = *(const uint4*)(pa + 8);
        rb0 = *(const uint4*)pb; rb1 = *(const uint4*)(pb + 8);
    }

    float acc[4][4][4];
#pragma unroll
    for (int i = 0; i < 4; i++)
#pragma unroll
        for (int j = 0; j < 4; j++)
#pragma unroll
            for (int k = 0; k < 4; k++) acc[i][j][k] = 0.f;

    uint32_t aoff[2][4], boff[2][4];
    {
        int g = lane >> 3, lr = lane & 7;
#pragma unroll
        for (int kk = 0; kk < 2; kk++)
#pragma unroll
            for (int fi = 0; fi < 4; fi++) {
                int row = wm + fi * 16 + (g & 1) * 8 + lr;
                int ch  = (kk * 2 + (g >> 1)) ^ ((row >> 1) & 3);
                aoff[kk][fi] = (uint32_t)(row * 32 + ch * 8) * 2;
            }
        int g2 = (lane >> 3) & 1;
#pragma unroll
        for (int kk = 0; kk < 2; kk++)
#pragma unroll
            for (int fj = 0; fj < 4; fj++) {
                int row = wn + fj * 8 + lr;
                int ch  = (kk * 2 + g2) ^ ((row >> 1) & 3);
                boff[kk][fj] = (uint32_t)(row * 32 + ch * 8) * 2;
            }
    }
    const uint32_t sAb[2] = { smem_u32(sA[0]), smem_u32(sA[1]) };
    const uint32_t sBb[2] = { smem_u32(sB[0]), smem_u32(sB[1]) };

    *(uint4*)(sA[0] + so0) = ra0; *(uint4*)(sA[0] + so1) = ra1;
    *(uint4*)(sB[0] + so0) = rb0; *(uint4*)(sB[0] + so1) = rb1;
    __syncthreads();

    for (int c = 0; c < TOT; c++) {
        int cur = c & 1;
        if (c + 1 < TOT) {
            int c1 = c + 1, p = c1 / CH, kc = (c1 - p * CH) * 32;
            const __nv_bfloat16* pa = ((p == 1) ? Al : Ah) + arow + kc;
            const __nv_bfloat16* pb = ((p == 2) ? Bl : Bh) + brow + kc;
            ra0 = *(const uint4*)pa; ra1 = *(const uint4*)(pa + 8);
            rb0 = *(const uint4*)pb; rb1 = *(const uint4*)(pb + 8);
        }
#pragma unroll
        for (int kk = 0; kk < 2; kk++) {
            uint32_t af[4][4], bf[4][2];
#pragma unroll
            for (int fi = 0; fi < 4; fi++) ldsm4(af[fi], sAb[cur] + aoff[kk][fi]);
#pragma unroll
            for (int fj = 0; fj < 4; fj++) ldsm2(bf[fj], sBb[cur] + boff[kk][fj]);
#pragma unroll
            for (int fi = 0; fi < 4; fi++)
#pragma unroll
                for (int fj = 0; fj < 4; fj++)
                    mma16816(acc[fi][fj], af[fi], bf[fj]);
        }
        if (c + 1 < TOT) {
            int nxt = cur ^ 1;
            *(uint4*)(sA[nxt] + so0) = ra0; *(uint4*)(sA[nxt] + so1) = ra1;
            *(uint4*)(sB[nxt] + so0) = rb0; *(uint4*)(sB[nxt] + so1) = rb1;
            __syncthreads();
        }
    }

    const int cr = lane >> 2, cc2 = (lane & 3) * 2;
    if (MODE == 0) {
#pragma unroll
        for (int fi = 0; fi < 4; fi++) {
            int r0 = m0 + wm + fi * 16 + cr;
#pragma unroll
            for (int fj = 0; fj < 4; fj++) {
                int nf = n0 + wn + fj * 8 + cc2;
                float b0 = bias[nf], b1 = bias[nf + 1];
                *(float2*)(Carg + (size_t)r0 * DD + nf) =
                    make_float2(acc[fi][fj][0] + b0, acc[fi][fj][1] + b1);
                *(float2*)(Carg + (size_t)(r0 + 8) * DD + nf) =
                    make_float2(acc[fi][fj][2] + b0, acc[fi][fj][3] + b1);
            }
        }
    } else {
        int part = n0 / DD;                 // 768 = 6*128: block never crosses
        __nv_bfloat16* dh = (part == 0) ? g_qh : (part == 1) ? g_kh : g_vh;
        __nv_bfloat16* dl = (part == 0) ? g_ql : (part == 1) ? g_kl : g_vl;
        float scl  = (part == 0) ? 0.125f : 1.f;   // hd^-0.5 on q
#pragma unroll
        for (int fi = 0; fi < 4; fi++) {
            int r0 = m0 + wm + fi * 16 + cr;
            int s0 = r0 >> 1, bi0 = r0 & 1;
            int r1 = r0 + 8;
            int s1 = r1 >> 1, bi1 = r1 & 1;
#pragma unroll
            for (int fj = 0; fj < 4; fj++) {
                int nf = n0 + wn + fj * 8 + cc2;
                float b0 = bias[nf], b1 = bias[nf + 1];
                int nip = nf - part * DD;
                int h = nip >> 6, ccn = nip & 63;
                size_t o0 = ((size_t)(bi0 * HH + h) * SS + s0) * HD + ccn;
                size_t o1 = ((size_t)(bi1 * HH + h) * SS + s1) * HD + ccn;
                uint32_t hh0, ll0, hh1, ll1;
                split2((acc[fi][fj][0] + b0) * scl, (acc[fi][fj][1] + b1) * scl, hh0, ll0);
                split2((acc[fi][fj][2] + b0) * scl, (acc[fi][fj][3] + b1) * scl, hh1, ll1);
                *(uint32_t*)&dh[o0] = hh0; *(uint32_t*)&dl[o0] = ll0;
                *(uint32_t*)&dh[o1] = hh1; *(uint32_t*)&dl[o1] = ll1;
            }
        }
    }
}

// ================= tensor-core flash attention =================
// block = (head, 128 q-rows), 8 warps x 16 rows; kv-tiles of 64.
// QK: QhKh + QlKh + QhKl; PV: PhVh + PlVh + PhVl (fp32 accum in registers)
__global__ __launch_bounds__(256) void attn_mma_kernel() {
    __shared__ __align__(16) __nv_bfloat16 smbuf[4 * 4096];   // 32 KB
    const uint32_t sb = smem_u32(smbuf);
    const int head = blockIdx.x, q0 = blockIdx.y * 128;
    const int t = threadIdx.x, lane = t & 31, wid = t >> 5;
    const int wq = wid * 16;
    const int lr = lane & 7, g = lane >> 3, g2 = g & 1;

    // ---- stage Q (Qh in u[0..1023], Ql in u[1024..2047]) ----
    {
        const __nv_bfloat16* qh = g_qh + ((size_t)head * SS + q0) * HD;
        const __nv_bfloat16* ql = g_ql + ((size_t)head * SS + q0) * HD;
        uint4* u = (uint4*)smbuf;
        for (int c = t; c < 1024; c += 256) {
            int row = c >> 3, ch = c & 7, ph = ch ^ (row & 7);
            u[row * 8 + ph]        = *(const uint4*)(qh + (size_t)row * HD + ch * 8);
            u[1024 + row * 8 + ph] = *(const uint4*)(ql + (size_t)row * HD + ch * 8);
        }
    }
    __syncthreads();
    uint32_t qhf[4][4], qlf[4][4];
#pragma unroll
    for (int ks = 0; ks < 4; ks++) {
        int row = wq + (g & 1) * 8 + lr;
        int ch = (ks * 2 + (g >> 1)) ^ (row & 7);
        ldsm4(qhf[ks], sb + (uint32_t)(row * 8 + ch) * 16);
        ldsm4(qlf[ks], sb + 16384u + (uint32_t)(row * 8 + ch) * 16);
    }

    float of[8][4];
#pragma unroll
    for (int fj = 0; fj < 8; fj++)
#pragma unroll
        for (int e = 0; e < 4; e++) of[fj][e] = 0.f;
    float m0 = __int_as_float(0xff800000), m1 = m0, l0 = 0.f, l1 = 0.f;

    for (int kv0 = 0; kv0 < SS; kv0 += 64) {
        __syncthreads();   // prior compute done reading smem (and Q frags loaded)
        {
            uint4* u = (uint4*)smbuf;
            const __nv_bfloat16* kh = g_kh + ((size_t)head * SS + kv0) * HD;
            const __nv_bfloat16* kl = g_kl + ((size_t)head * SS + kv0) * HD;
            const __nv_bfloat16* vh = g_vh + ((size_t)head * SS + kv0) * HD;
            const __nv_bfloat16* vl = g_vl + ((size_t)head * SS + kv0) * HD;
            for (int c = t; c < 512; c += 256) {
                int row = c >> 3, ch = c & 7, ph = ch ^ (row & 7);
                int idx = row * 8 + ph;
                size_t go = (size_t)row * HD + ch * 8;
                u[idx]        = *(const uint4*)(kh + go);
                u[512 + idx]  = *(const uint4*)(kl + go);
                u[1024 + idx] = *(const uint4*)(vh + go);
                u[1536 + idx] = *(const uint4*)(vl + go);
            }
        }
        __syncthreads();

        // ---- S = Q K^T (3-pass split) ----
        float sf[8][4];
#pragma unroll
        for (int fj = 0; fj < 8; fj++)
#pragma unroll
            for (int e = 0; e < 4; e++) sf[fj][e] = 0.f;
#pragma unroll
        for (int ks = 0; ks < 4; ks++) {
            uint32_t kb[8][2];
#pragma unroll
            for (int fj = 0; fj < 8; fj++) {
                int row = fj * 8 + lr;
                int ch = (ks * 2 + g2) ^ (row & 7);
                ldsm2(kb[fj], sb + (uint32_t)(row * 8 + ch) * 16);
            }
#pragma unroll
            for (int fj = 0; fj < 8; fj++) mma16816(sf[fj], qhf[ks], kb[fj]);
#pragma unroll
            for (int fj = 0; fj < 8; fj++) mma16816(sf[fj], qlf[ks], kb[fj]);
#pragma unroll
            for (int fj = 0; fj < 8; fj++) {
                int row = fj * 8 + lr;
                int ch = (ks * 2 + g2) ^ (row & 7);
                ldsm2(kb[fj], sb + 8192u + (uint32_t)(row * 8 + ch) * 16);
            }
#pragma unroll
            for (int fj = 0; fj < 8; fj++) mma16816(sf[fj], qhf[ks], kb[fj]);
        }

        // ---- online softmax (row0 = d0/d1, row1 = d2/d3; 4-lane groups) ----
        float mx0 = __int_as_float(0xff800000), mx1 = mx0;
#pragma unroll
        for (int fj = 0; fj < 8; fj++) {
            mx0 = fmaxf(mx0, fmaxf(sf[fj][0], sf[fj][1]));
            mx1 = fmaxf(mx1, fmaxf(sf[fj][2], sf[fj][3]));
        }
#pragma unroll
        for (int off = 1; off < 4; off <<= 1) {
            mx0 = fmaxf(mx0, __shfl_xor_sync(0xffffffffu, mx0, off));
            mx1 = fmaxf(mx1, __shfl_xor_sync(0xffffffffu, mx1, off));
        }
        float mn0 = fmaxf(m0, mx0), mn1 = fmaxf(m1, mx1);
        float s0 = 0.f, s1 = 0.f;
#pragma unroll
        for (int fj = 0; fj < 8; fj++) {
            sf[fj][0] = __expf(sf[fj][0] - mn0); s0 += sf[fj][0];
            sf[fj][1] = __expf(sf[fj][1] - mn0); s0 += sf[fj][1];
            sf[fj][2] = __expf(sf[fj][2] - mn1); s1 += sf[fj][2];
            sf[fj][3] = __expf(sf[fj][3] - mn1); s1 += sf[fj][3];
        }
#pragma unroll
        for (int off = 1; off < 4; off <<= 1) {
            s0 += __shfl_xor_sync(0xffffffffu, s0, off);
            s1 += __shfl_xor_sync(0xffffffffu, s1, off);
        }
        float a0 = __expf(m0 - mn0), a1 = __expf(m1 - mn1);
        l0 = l0 * a0 + s0; l1 = l1 * a1 + s1; m0 = mn0; m1 = mn1;
#pragma unroll
        for (int fj = 0; fj < 8; fj++) {
            of[fj][0] *= a0; of[fj][1] *= a0;
            of[fj][2] *= a1; of[fj][3] *= a1;
        }

        // ---- O += P V (3-pass split; P a-frags built in-register) ----
#pragma unroll
        for (int ks = 0; ks < 4; ks++) {
            uint32_t pah[4], pal[4];
            split2(sf[2*ks][0],   sf[2*ks][1],   pah[0], pal[0]);
            split2(sf[2*ks][2],   sf[2*ks][3],   pah[1], pal[1]);
            split2(sf[2*ks+1][0], sf[2*ks+1][1], pah[2], pal[2]);
            split2(sf[2*ks+1][2], sf[2*ks+1][3], pah[3], pal[3]);
            uint32_t vb[8][2];
            int vrow = ks * 16 + g2 * 8 + lr;
#pragma unroll
            for (int fj = 0; fj < 8; fj++) {
                int ch = fj ^ (vrow & 7);
                ldsm2t(vb[fj], sb + 16384u + (uint32_t)(vrow * 8 + ch) * 16);
            }
#pragma unroll
            for (int fj = 0; fj < 8; fj++) mma16816(of[fj], pah, vb[fj]);
#pragma unroll
            for (int fj = 0; fj < 8; fj++) mma16816(of[fj], pal, vb[fj]);
#pragma unroll
            for (int fj = 0; fj < 8; fj++) {
                int ch = fj ^ (vrow & 7);
                ldsm2t(vb[fj], sb + 24576u + (uint32_t)(vrow * 8 + ch) * 16);
            }
#pragma unroll
            for (int fj = 0; fj < 8; fj++) mma16816(of[fj], pah, vb[fj]);
        }
    }

    // ---- epilogue: normalize and write fp32 + bf16 hi/lo ----
    float inv0 = 1.f / l0, inv1 = 1.f / l1;
    int b = head / HH, hh = head - b * HH;
    int r0 = q0 + wq + (lane >> 2), r1 = r0 + 8;
    size_t ro0 = (size_t)(r0 * BB + b) * KA + hh * HD + (lane & 3) * 2;
    size_t ro1 = (size_t)(r1 * BB + b) * KA + hh * HD + (lane & 3) * 2;
#pragma unroll
    for (int fj = 0; fj < 8; fj++) {
        float x0 = of[fj][0] * inv0, y0 = of[fj][1] * inv0;
        float x1 = of[fj][2] * inv1, y1 = of[fj][3] * inv1;
        *(float2*)&g_A2[ro0 + fj * 8] = make_float2(x0, y0);
        *(float2*)&g_A2[ro1 + fj * 8] = make_float2(x1, y1);
        uint32_t h, lo;
        split2(x0, y0, h, lo);
        *(uint32_t*)&g_A2h[ro0 + fj * 8] = h; *(uint32_t*)&g_A2l[ro0 + fj * 8] = lo;
        split2(x1, y1, h, lo);
        *(uint32_t*)&g_A2h[ro1 + fj * 8] = h; *(uint32_t*)&g_A2l[ro1 + fj * 8] = lo;
    }
}

// ================= launch =================
extern "C" void kernel_launch(void* const* d_in, const int* in_sizes, int n_in,
                              void* d_out, int out_size) {
    const float* query   = (const float*)d_in[0];
    // d_in[1] key, d_in[2] value: unused by reference (self-attn on query)
    const float* ipw     = (const float*)d_in[3];
    const float* ipb     = (const float*)d_in[4];
    const float* sc1     = (const float*)d_in[5];
    const float* sh1     = (const float*)d_in[6];
    const float* l1dw    = (const float*)d_in[7];
    const float* l1db    = (const float*)d_in[8];
    const float* l1uw    = (const float*)d_in[9];
    const float* l1ub    = (const float*)d_in[10];
    const float* l1s     = (const float*)d_in[11];
    const float* outw    = (const float*)d_in[12];
    const float* outb    = (const float*)d_in[13];
    const float* sc2     = (const float*)d_in[14];
    const float* sh2     = (const float*)d_in[15];
    const float* l2dw    = (const float*)d_in[16];
    const float* l2db    = (const float*)d_in[17];
    const float* l2uw    = (const float*)d_in[18];
    const float* l2ub    = (const float*)d_in[19];
    const float* l2s     = (const float*)d_in[20];
    float* out = (float*)d_out;

    pack_query_kernel<<<(MM * DD / 4 + 255) / 256, 256>>>(query);
    gemm64_kernel<1><<<dim3(1, MM / 32), 256>>>(query, l1dw, l1db);
    prep_wqkv_kernel<<<(E3 * KA + 255) / 256, 256>>>(ipw, ipb, sc1, sh1, l1uw, l1ub, l1s);
    gemm_mma_kernel<2><<<dim3(E3 / 128, MM / 128), 256>>>(nullptr);
    attn_mma_kernel<<<dim3(NHEAD, SS / 128), 256>>>();
    gemm64_kernel<3><<<dim3(1, MM / 32), 256>>>(nullptr, l2dw, l2db);
    prep_wout_kernel<<<(DD * KA + 255) / 256, 256>>>(outw, outb, sc2, sh2, l2uw, l2ub, l2s);
    gemm_mma_kernel<0><<<dim3(DD / 128, MM / 128), 256>>>(out);
}